// round 1
// baseline (speedup 1.0000x reference)
#include <cuda_runtime.h>
#include <cstdint>

#define NMAX 100000
#define EMAX 1600000
#define HID 128
#define HEADS 8
#define NLAYERS 6

// ---------------- scratch (device globals; no allocation allowed) ----------------
__device__ __align__(16) float g_hA[(size_t)NMAX * HID];
__device__ __align__(16) float g_hB[(size_t)NMAX * HID];
__device__ __align__(16) float g_hp[(size_t)NMAX * HID];
__device__ __align__(16) float g_as[(size_t)NMAX * HEADS];
__device__ __align__(16) float g_ad[(size_t)NMAX * HEADS];
__device__ int g_off[NMAX + 1];
__device__ int g_deg[NMAX];
__device__ int g_cnt[NMAX];
__device__ int g_bsum[256];
__device__ int g_eid[EMAX];
__device__ int g_srcS[EMAX];
__device__ __align__(16) float4 g_eaS[EMAX];
__device__ float g_wsd[NLAYERS * 16 * HID];   // [l][j(0..7=src,8..15=dst)][k]
__device__ float g_weh[NLAYERS * 4 * HEADS];  // [l][d][h]

// ---------------- utils ----------------
__device__ __forceinline__ float warp_sum(float v) {
#pragma unroll
    for (int o = 16; o; o >>= 1) v += __shfl_xor_sync(0xffffffffu, v, o);
    return v;
}

// ---------------- preprocessing ----------------
__global__ void k_zero(int n) {
    int i = blockIdx.x * blockDim.x + threadIdx.x;
    if (i < n) { g_deg[i] = 0; g_cnt[i] = 0; }
}

__global__ void k_hist(const int* __restrict__ ei, int Ee) {
    int e = blockIdx.x * blockDim.x + threadIdx.x;
    if (e < Ee) atomicAdd(&g_deg[ei[Ee + e]], 1);
}

// block-wise exclusive scan of g_deg into g_off, block totals to g_bsum
__global__ void k_scan1(int n) {
    __shared__ int ws[32];
    int i = blockIdx.x * 1024 + threadIdx.x;
    int lane = threadIdx.x & 31, wid = threadIdx.x >> 5;
    int v = (i < n) ? g_deg[i] : 0;
    int x = v;
#pragma unroll
    for (int o = 1; o < 32; o <<= 1) {
        int y = __shfl_up_sync(0xffffffffu, x, o);
        if (lane >= o) x += y;
    }
    if (lane == 31) ws[wid] = x;
    __syncthreads();
    if (wid == 0) {
        int y = ws[lane];
#pragma unroll
        for (int o = 1; o < 32; o <<= 1) {
            int z = __shfl_up_sync(0xffffffffu, y, o);
            if (lane >= o) y += z;
        }
        ws[lane] = y;
    }
    __syncthreads();
    int inc = x + (wid > 0 ? ws[wid - 1] : 0);
    if (i < n) g_off[i] = inc - v;
    if (threadIdx.x == 1023) g_bsum[blockIdx.x] = inc;
}

__global__ void k_scan2(int nb) {
    int run = 0;
    for (int b = 0; b < nb; b++) { int t = g_bsum[b]; g_bsum[b] = run; run += t; }
    g_bsum[nb] = run;
}

__global__ void k_scan3(int n) {
    int i = blockIdx.x * 1024 + threadIdx.x;
    if (i < n) g_off[i] += g_bsum[blockIdx.x];
    if (i == 0) g_off[n] = g_bsum[gridDim.x];
}

__global__ void k_scatter(const int* __restrict__ ei, int Ee) {
    int e = blockIdx.x * blockDim.x + threadIdx.x;
    if (e >= Ee) return;
    int d = ei[Ee + e];
    int p = g_off[d] + atomicAdd(&g_cnt[d], 1);
    g_eid[p] = e;
}

// per-node sort of edge ids (restores determinism after atomic scatter),
// then materialize src_sorted + permuted edge_attr.
__global__ void k_sortfix(const int* __restrict__ ei, const float4* __restrict__ ea, int Nn) {
    int n = blockIdx.x * blockDim.x + threadIdx.x;
    if (n >= Nn) return;
    int st = g_off[n], en = g_off[n + 1];
    int d = en - st;
    if (d <= 0) return;
    if (d <= 192) {
        int a[192];
        for (int i = 0; i < d; i++) a[i] = g_eid[st + i];
        for (int i = 1; i < d; i++) {
            int key = a[i]; int j = i - 1;
            while (j >= 0 && a[j] > key) { a[j + 1] = a[j]; j--; }
            a[j + 1] = key;
        }
        for (int i = 0; i < d; i++) {
            int eid = a[i];
            g_srcS[st + i] = ei[eid];
            g_eaS[st + i] = ea[eid];
        }
    } else {
        for (int i = 0; i < d - 1; i++) {
            int mn = i;
            for (int j = i + 1; j < d; j++)
                if (g_eid[st + j] < g_eid[st + mn]) mn = j;
            int t = g_eid[st + i]; g_eid[st + i] = g_eid[st + mn]; g_eid[st + mn] = t;
        }
        for (int i = 0; i < d; i++) {
            int eid = g_eid[st + i];
            g_srcS[st + i] = ei[eid];
            g_eaS[st + i] = ea[eid];
        }
    }
}

// fold attention vectors into per-layer matrices:
// wsd[l][h][k]   = sum_c Wg[l][k][h*16+c]*att_src[l][h][c]
// wsd[l][8+h][k] = ... att_dst
// weh[l][d][h]   = sum_c We[l][d][h*16+c]*att_edge[l][h][c]
__global__ void k_prep_w(const float* __restrict__ Wg, const float* __restrict__ asv,
                         const float* __restrict__ adv, const float* __restrict__ We,
                         const float* __restrict__ aev) {
    int l = blockIdx.x;
    int k = threadIdx.x;  // 128
    const float* W = Wg + (size_t)l * HID * HID;
#pragma unroll
    for (int h = 0; h < HEADS; h++) {
        float s = 0.f, d = 0.f;
#pragma unroll
        for (int c = 0; c < 16; c++) {
            float w = W[k * HID + h * 16 + c];
            s += w * asv[l * HID + h * 16 + c];
            d += w * adv[l * HID + h * 16 + c];
        }
        g_wsd[l * 2048 + h * HID + k] = s;
        g_wsd[l * 2048 + (8 + h) * HID + k] = d;
    }
    if (k < 4) {
#pragma unroll
        for (int h = 0; h < HEADS; h++) {
            float s = 0.f;
#pragma unroll
            for (int c = 0; c < 16; c++)
                s += We[l * 4 * HID + k * HID + h * 16 + c] * aev[l * HID + h * 16 + c];
            g_weh[l * 32 + k * 8 + h] = s;
        }
    }
}

// ---------------- input projection: h0 = LN(relu(x @ W_in + b_in)) ----------------
__global__ void k_input(const float* __restrict__ x, const float* __restrict__ Win,
                        const float* __restrict__ bin, const float* __restrict__ g,
                        const float* __restrict__ b, float* __restrict__ h0, int Nn) {
    __shared__ float Ws[16 * HID];
    for (int i = threadIdx.x; i < 16 * HID; i += blockDim.x) Ws[i] = Win[i];
    __syncthreads();
    int gw = (blockIdx.x * blockDim.x + threadIdx.x) >> 5;
    if (gw >= Nn) return;
    int lane = threadIdx.x & 31;
    float4 bv = ((const float4*)bin)[lane];
    float acc0 = bv.x, acc1 = bv.y, acc2 = bv.z, acc3 = bv.w;
#pragma unroll
    for (int k = 0; k < 16; k++) {
        float xv = __ldg(x + (size_t)gw * 16 + k);
        acc0 += xv * Ws[k * HID + lane * 4 + 0];
        acc1 += xv * Ws[k * HID + lane * 4 + 1];
        acc2 += xv * Ws[k * HID + lane * 4 + 2];
        acc3 += xv * Ws[k * HID + lane * 4 + 3];
    }
    float t0 = fmaxf(acc0, 0.f), t1 = fmaxf(acc1, 0.f), t2 = fmaxf(acc2, 0.f), t3 = fmaxf(acc3, 0.f);
    float sm = warp_sum(t0 + t1 + t2 + t3);
    float sq = warp_sum(t0 * t0 + t1 * t1 + t2 * t2 + t3 * t3);
    float mu = sm * (1.f / 128.f);
    float var = sq * (1.f / 128.f) - mu * mu;
    float rs = rsqrtf(var + 1e-5f);
    float4 gv = ((const float4*)g)[lane];
    float4 bbv = ((const float4*)b)[lane];
    float4 o;
    o.x = (t0 - mu) * rs * gv.x + bbv.x;
    o.y = (t1 - mu) * rs * gv.y + bbv.y;
    o.z = (t2 - mu) * rs * gv.z + bbv.z;
    o.w = (t3 - mu) * rs * gv.w + bbv.w;
    ((float4*)(h0 + (size_t)gw * HID))[lane] = o;
}

// ---------------- fp32 tiled GEMM: C[M,128] = A[M,128] @ B[128,128] (+bias+relu) ----
template <bool BRELU>
__global__ void __launch_bounds__(128) k_gemm128(const float* __restrict__ A,
                                                 const float* __restrict__ Bm,
                                                 const float* __restrict__ bias,
                                                 float* __restrict__ C, int M) {
    __shared__ float As[16][64];
    __shared__ float Bs[16][128];
    const int tid = threadIdx.x;
    const int m0 = blockIdx.x * 64;
    const int tx = tid & 15;  // col group: cols tx*8..tx*8+7
    const int ty = tid >> 4;  // row group: rows ty*8..ty*8+7
    float acc[8][8];
#pragma unroll
    for (int i = 0; i < 8; i++)
#pragma unroll
        for (int j = 0; j < 8; j++) acc[i][j] = 0.f;

    const int mr = tid >> 2;
    const int kc = (tid & 3) * 4;
    for (int k0 = 0; k0 < 128; k0 += 16) {
#pragma unroll
        for (int p = 0; p < 2; p++) {
            int m = m0 + mr + p * 32;
            float4 v = make_float4(0.f, 0.f, 0.f, 0.f);
            if (m < M) v = *(const float4*)(A + (size_t)m * HID + k0 + kc);
            As[kc + 0][mr + p * 32] = v.x;
            As[kc + 1][mr + p * 32] = v.y;
            As[kc + 2][mr + p * 32] = v.z;
            As[kc + 3][mr + p * 32] = v.w;
        }
#pragma unroll
        for (int p = 0; p < 4; p++) {
            int idx = tid + p * 128;
            int kr = idx >> 5;
            int n4 = (idx & 31) * 4;
            *(float4*)&Bs[kr][n4] = *(const float4*)(Bm + (size_t)(k0 + kr) * HID + n4);
        }
        __syncthreads();
#pragma unroll
        for (int kk = 0; kk < 16; kk++) {
            float a[8], bb[8];
            *(float4*)(a) = *(float4*)&As[kk][ty * 8];
            *(float4*)(a + 4) = *(float4*)&As[kk][ty * 8 + 4];
            *(float4*)(bb) = *(float4*)&Bs[kk][tx * 8];
            *(float4*)(bb + 4) = *(float4*)&Bs[kk][tx * 8 + 4];
#pragma unroll
            for (int i = 0; i < 8; i++)
#pragma unroll
                for (int j = 0; j < 8; j++) acc[i][j] = fmaf(a[i], bb[j], acc[i][j]);
        }
        __syncthreads();
    }
    float bv[8];
    if (BRELU) {
#pragma unroll
        for (int j = 0; j < 8; j++) bv[j] = bias[tx * 8 + j];
    }
#pragma unroll
    for (int i = 0; i < 8; i++) {
        int m = m0 + ty * 8 + i;
        if (m >= M) break;
        float o[8];
#pragma unroll
        for (int j = 0; j < 8; j++) {
            float v = acc[i][j];
            if (BRELU) v = fmaxf(v + bv[j], 0.f);
            o[j] = v;
        }
        *(float4*)(C + (size_t)m * HID + tx * 8) = *(float4*)o;
        *(float4*)(C + (size_t)m * HID + tx * 8 + 4) = *(float4*)(o + 4);
    }
}

// ---------------- alpha_src / alpha_dst: h @ wsd[l] ----------------
__global__ void k_asad(const float* __restrict__ h, const float* __restrict__ wsd_l, int Nn) {
    __shared__ float w[2048];
    for (int i = threadIdx.x; i < 2048; i += blockDim.x) w[i] = wsd_l[i];
    __syncthreads();
    int gw = (blockIdx.x * blockDim.x + threadIdx.x) >> 5;
    if (gw >= Nn) return;
    int lane = threadIdx.x & 31;
    float hr[4];
#pragma unroll
    for (int i = 0; i < 4; i++) hr[i] = h[(size_t)gw * HID + lane + 32 * i];
#pragma unroll
    for (int j = 0; j < 16; j++) {
        float p = 0.f;
#pragma unroll
        for (int i = 0; i < 4; i++) p += hr[i] * w[j * HID + lane + 32 * i];
        p = warp_sum(p);
        if (lane == 0) {
            if (j < 8) g_as[(size_t)gw * 8 + j] = p;
            else g_ad[(size_t)gw * 8 + j - 8] = p;
        }
    }
}

// ---------------- fused attention + aggregation + residual + LN ----------------
__global__ void k_gat_edge(const float* __restrict__ hcur, const float* __restrict__ weh_l,
                           const float* __restrict__ bgl, const float* __restrict__ lng,
                           const float* __restrict__ lnb, float* __restrict__ hnext, int Nn) {
    int gw = (blockIdx.x * blockDim.x + threadIdx.x) >> 5;
    if (gw >= Nn) return;
    int lane = threadIdx.x & 31;
    int hh = lane >> 2;  // head 0..7, lane covers channels 4*lane..4*lane+3
    float adv = __ldg(&g_ad[(size_t)gw * 8 + hh]);
    float w0 = __ldg(&weh_l[0 * 8 + hh]);
    float w1 = __ldg(&weh_l[1 * 8 + hh]);
    float w2 = __ldg(&weh_l[2 * 8 + hh]);
    float w3 = __ldg(&weh_l[3 * 8 + hh]);
    int s0 = g_off[gw], s1 = g_off[gw + 1];
    float ax = 0.f, ay = 0.f, az = 0.f, aw = 0.f, den = 0.f;
    for (int e = s0; e < s1; ++e) {
        int s = __ldg(&g_srcS[e]);
        float asv = __ldg(&g_as[(size_t)s * 8 + hh]);
        float4 eav = g_eaS[e];
        float al = asv + adv + eav.x * w0 + eav.y * w1 + eav.z * w2 + eav.w * w3;
        al = al > 0.f ? al : 0.2f * al;
        float a = __expf(al);
        den += a;
        float4 hv = *(const float4*)(g_hp + (size_t)s * HID + lane * 4);
        ax = fmaf(a, hv.x, ax);
        ay = fmaf(a, hv.y, ay);
        az = fmaf(a, hv.z, az);
        aw = fmaf(a, hv.w, aw);
    }
    float r = 1.f / (den + 1e-16f);
    float4 hc = *(const float4*)(hcur + (size_t)gw * HID + lane * 4);
    float4 bgv = ((const float4*)bgl)[lane];
    float t0 = hc.x + ax * r + bgv.x;
    float t1 = hc.y + ay * r + bgv.y;
    float t2 = hc.z + az * r + bgv.z;
    float t3 = hc.w + aw * r + bgv.w;
    float sm = warp_sum(t0 + t1 + t2 + t3);
    float sq = warp_sum(t0 * t0 + t1 * t1 + t2 * t2 + t3 * t3);
    float mu = sm * (1.f / 128.f);
    float var = sq * (1.f / 128.f) - mu * mu;
    float rs = rsqrtf(var + 1e-5f);
    float4 gv = ((const float4*)lng)[lane];
    float4 bbv = ((const float4*)lnb)[lane];
    float4 o;
    o.x = (t0 - mu) * rs * gv.x + bbv.x;
    o.y = (t1 - mu) * rs * gv.y + bbv.y;
    o.z = (t2 - mu) * rs * gv.z + bbv.z;
    o.w = (t3 - mu) * rs * gv.w + bbv.w;
    ((float4*)(hnext + (size_t)gw * HID))[lane] = o;
}

// ---------------- output head 2: out = relu(t @ W2 + b2), OUT_DIM=3 ----------------
__global__ void k_out2(const float* __restrict__ t, const float* __restrict__ W2,
                       const float* __restrict__ b2, float* __restrict__ out, int Nn) {
    __shared__ float w[HID * 3];
    for (int i = threadIdx.x; i < HID * 3; i += blockDim.x) w[i] = W2[i];
    __syncthreads();
    int gw = (blockIdx.x * blockDim.x + threadIdx.x) >> 5;
    if (gw >= Nn) return;
    int lane = threadIdx.x & 31;
    float p0 = 0.f, p1 = 0.f, p2 = 0.f;
#pragma unroll
    for (int i = 0; i < 4; i++) {
        int k = lane + 32 * i;
        float v = t[(size_t)gw * HID + k];
        p0 += v * w[k * 3 + 0];
        p1 += v * w[k * 3 + 1];
        p2 += v * w[k * 3 + 2];
    }
    p0 = warp_sum(p0); p1 = warp_sum(p1); p2 = warp_sum(p2);
    if (lane == 0) {
        out[(size_t)gw * 3 + 0] = fmaxf(p0 + __ldg(&b2[0]), 0.f);
        out[(size_t)gw * 3 + 1] = fmaxf(p1 + __ldg(&b2[1]), 0.f);
        out[(size_t)gw * 3 + 2] = fmaxf(p2 + __ldg(&b2[2]), 0.f);
    }
}

// ---------------- launch ----------------
extern "C" void kernel_launch(void* const* d_in, const int* in_sizes, int n_in,
                              void* d_out, int out_size) {
    const float* x = (const float*)d_in[0];
    const int* ei = (const int*)d_in[1];
    const float* ea = (const float*)d_in[2];
    const float* W_in = (const float*)d_in[3];
    const float* b_in = (const float*)d_in[4];
    const float* ln_in_g = (const float*)d_in[5];
    const float* ln_in_b = (const float*)d_in[6];
    const float* Wg = (const float*)d_in[7];
    const float* att_src = (const float*)d_in[8];
    const float* att_dst = (const float*)d_in[9];
    const float* We = (const float*)d_in[10];
    const float* att_edge = (const float*)d_in[11];
    const float* bg = (const float*)d_in[12];
    const float* ln_g = (const float*)d_in[13];
    const float* ln_b = (const float*)d_in[14];
    const float* W1 = (const float*)d_in[15];
    const float* b1 = (const float*)d_in[16];
    const float* W2 = (const float*)d_in[17];
    const float* b2 = (const float*)d_in[18];

    int Nn = in_sizes[0] / 16;      // 100000
    int Ee = in_sizes[2] / 4;       // 1600000

    // symbol addresses (host-side queries; no allocation, graph-capture safe)
    float *hA, *hB, *hp, *wsd, *weh;
    cudaGetSymbolAddress((void**)&hA, g_hA);
    cudaGetSymbolAddress((void**)&hB, g_hB);
    cudaGetSymbolAddress((void**)&hp, g_hp);
    cudaGetSymbolAddress((void**)&wsd, g_wsd);
    cudaGetSymbolAddress((void**)&weh, g_weh);

    // ---- preprocessing: CSR by dst, deterministic order ----
    k_zero<<<(Nn + 255) / 256, 256>>>(Nn);
    k_hist<<<(Ee + 255) / 256, 256>>>(ei, Ee);
    int nb = (Nn + 1023) / 1024;
    k_scan1<<<nb, 1024>>>(Nn);
    k_scan2<<<1, 1>>>(nb);
    k_scan3<<<nb, 1024>>>(Nn);
    k_scatter<<<(Ee + 255) / 256, 256>>>(ei, Ee);
    k_sortfix<<<(Nn + 255) / 256, 256>>>(ei, (const float4*)ea, Nn);

    // ---- fold attention vectors (all layers) ----
    k_prep_w<<<NLAYERS, 128>>>(Wg, att_src, att_dst, We, att_edge);

    // ---- input projection ----
    int nwb = (Nn + 7) / 8;  // 8 warps per 256-thread block
    k_input<<<nwb, 256>>>(x, W_in, b_in, ln_in_g, ln_in_b, hA, Nn);

    // ---- GAT layers ----
    float* hcur = hA;
    float* hnxt = hB;
    int gblocks = (Nn + 63) / 64;
    for (int l = 0; l < NLAYERS; l++) {
        k_gemm128<false><<<gblocks, 128>>>(hcur, Wg + (size_t)l * HID * HID, nullptr, hp, Nn);
        k_asad<<<nwb, 256>>>(hcur, wsd + l * 2048, Nn);
        k_gat_edge<<<nwb, 256>>>(hcur, weh + l * 32, bg + l * HID,
                                 ln_g + l * HID, ln_b + l * HID, hnxt, Nn);
        float* t = hcur; hcur = hnxt; hnxt = t;
    }

    // ---- output head ----
    k_gemm128<true><<<gblocks, 128>>>(hcur, W1, b1, hp, Nn);
    k_out2<<<nwb, 256>>>(hp, W2, b2, (float*)d_out, Nn);
}

// round 3
// speedup vs baseline: 1.5286x; 1.5286x over previous
#include <cuda_runtime.h>
#include <cuda_bf16.h>
#include <cstdint>

#define NMAX 100000
#define EMAX 1600000
#define HID 128
#define HEADS 8
#define NLAYERS 6

// ---------------- scratch (device globals; no allocation allowed) ----------------
__device__ __align__(16) float g_hA[(size_t)NMAX * HID];
__device__ __align__(16) float g_hB[(size_t)NMAX * HID];
__device__ __align__(16) float g_hp[(size_t)NMAX * HID];
__device__ __align__(16) float g_as[(size_t)NMAX * HEADS];
__device__ __align__(16) float g_ad[(size_t)NMAX * HEADS];
__device__ int g_off[NMAX + 1];
__device__ int g_deg[NMAX];
__device__ int g_cnt[NMAX];
__device__ int g_bsum[256];
__device__ int g_eid[EMAX];
__device__ int g_srcS[EMAX];
__device__ __align__(16) float4 g_eaS[EMAX];
__device__ float g_weh[NLAYERS * 4 * HEADS];  // [l][d][h]
// pre-split transposed weights: [7][n=128][k=128] bf16 (6 GAT layers + W1)
__device__ __align__(16) __nv_bfloat16 g_Bh[7 * 128 * 128];
__device__ __align__(16) __nv_bfloat16 g_Bl[7 * 128 * 128];

// ---------------- utils ----------------
__device__ __forceinline__ float warp_sum(float v) {
#pragma unroll
    for (int o = 16; o; o >>= 1) v += __shfl_xor_sync(0xffffffffu, v, o);
    return v;
}

__device__ __forceinline__ void mma16816(float* d, uint32_t a0, uint32_t a1, uint32_t a2,
                                         uint32_t a3, uint32_t b0, uint32_t b1) {
    asm volatile(
        "mma.sync.aligned.m16n8k16.row.col.f32.bf16.bf16.f32 "
        "{%0,%1,%2,%3}, {%4,%5,%6,%7}, {%8,%9}, {%0,%1,%2,%3};"
        : "+f"(d[0]), "+f"(d[1]), "+f"(d[2]), "+f"(d[3])
        : "r"(a0), "r"(a1), "r"(a2), "r"(a3), "r"(b0), "r"(b1));
}

// ---------------- preprocessing ----------------
__global__ void k_zero(int n) {
    int i = blockIdx.x * blockDim.x + threadIdx.x;
    if (i < n) { g_deg[i] = 0; g_cnt[i] = 0; }
}

__global__ void k_hist(const int* __restrict__ ei, int Ee) {
    int e = blockIdx.x * blockDim.x + threadIdx.x;
    if (e < Ee) atomicAdd(&g_deg[ei[Ee + e]], 1);
}

__global__ void k_scan1(int n) {
    __shared__ int ws[32];
    int i = blockIdx.x * 1024 + threadIdx.x;
    int lane = threadIdx.x & 31, wid = threadIdx.x >> 5;
    int v = (i < n) ? g_deg[i] : 0;
    int x = v;
#pragma unroll
    for (int o = 1; o < 32; o <<= 1) {
        int y = __shfl_up_sync(0xffffffffu, x, o);
        if (lane >= o) x += y;
    }
    if (lane == 31) ws[wid] = x;
    __syncthreads();
    if (wid == 0) {
        int y = ws[lane];
#pragma unroll
        for (int o = 1; o < 32; o <<= 1) {
            int z = __shfl_up_sync(0xffffffffu, y, o);
            if (lane >= o) y += z;
        }
        ws[lane] = y;
    }
    __syncthreads();
    int inc = x + (wid > 0 ? ws[wid - 1] : 0);
    if (i < n) g_off[i] = inc - v;
    if (threadIdx.x == 1023) g_bsum[blockIdx.x] = inc;
}

__global__ void k_scan2(int nb) {
    int run = 0;
    for (int b = 0; b < nb; b++) { int t = g_bsum[b]; g_bsum[b] = run; run += t; }
    g_bsum[nb] = run;
}

__global__ void k_scan3(int n) {
    int i = blockIdx.x * 1024 + threadIdx.x;
    if (i < n) g_off[i] += g_bsum[blockIdx.x];
    if (i == 0) g_off[n] = g_bsum[gridDim.x];
}

__global__ void k_scatter(const int* __restrict__ ei, int Ee) {
    int e = blockIdx.x * blockDim.x + threadIdx.x;
    if (e >= Ee) return;
    int d = ei[Ee + e];
    int p = g_off[d] + atomicAdd(&g_cnt[d], 1);
    g_eid[p] = e;
}

__global__ void k_sortfix(const int* __restrict__ ei, const float4* __restrict__ ea, int Nn) {
    int n = blockIdx.x * blockDim.x + threadIdx.x;
    if (n >= Nn) return;
    int st = g_off[n], en = g_off[n + 1];
    int d = en - st;
    if (d <= 0) return;
    if (d <= 192) {
        int a[192];
        for (int i = 0; i < d; i++) a[i] = g_eid[st + i];
        for (int i = 1; i < d; i++) {
            int key = a[i]; int j = i - 1;
            while (j >= 0 && a[j] > key) { a[j + 1] = a[j]; j--; }
            a[j + 1] = key;
        }
        for (int i = 0; i < d; i++) {
            int eid = a[i];
            g_srcS[st + i] = ei[eid];
            g_eaS[st + i] = ea[eid];
        }
    } else {
        for (int i = 0; i < d - 1; i++) {
            int mn = i;
            for (int j = i + 1; j < d; j++)
                if (g_eid[st + j] < g_eid[st + mn]) mn = j;
            int t = g_eid[st + i]; g_eid[st + i] = g_eid[st + mn]; g_eid[st + mn] = t;
        }
        for (int i = 0; i < d; i++) {
            int eid = g_eid[st + i];
            g_srcS[st + i] = ei[eid];
            g_eaS[st + i] = ea[eid];
        }
    }
}

// edge attention weights folded per layer
__global__ void k_prep_weh(const float* __restrict__ We, const float* __restrict__ aev) {
    int l = blockIdx.x;
    int t = threadIdx.x;  // 32
    int d = t >> 3, h = t & 7;
    float s = 0.f;
#pragma unroll
    for (int c = 0; c < 16; c++)
        s += We[l * 4 * HID + d * HID + h * 16 + c] * aev[l * HID + h * 16 + c];
    g_weh[l * 32 + d * 8 + h] = s;
}

// transpose + bf16-split weights: g_Bh[l][n][k] = bf16(W[k][n]); g_Bl = residual
__global__ void k_prep_bsplit(const float* __restrict__ Wg, const float* __restrict__ W1) {
    int l = blockIdx.x;
    const float* W = (l < NLAYERS) ? (Wg + (size_t)l * HID * HID) : W1;
    int n = threadIdx.x;
    __nv_bfloat16* bh = g_Bh + (size_t)l * HID * HID;
    __nv_bfloat16* bl = g_Bl + (size_t)l * HID * HID;
    for (int k = 0; k < HID; k++) {
        float v = W[k * HID + n];
        __nv_bfloat16 hb = __float2bfloat16(v);
        float r = v - __bfloat162float(hb);
        bh[n * HID + k] = hb;
        bl[n * HID + k] = __float2bfloat16(r);
    }
}

// ---------------- input projection: h0 = LN(relu(x @ W_in + b_in)) ----------------
__global__ void k_input(const float* __restrict__ x, const float* __restrict__ Win,
                        const float* __restrict__ bin, const float* __restrict__ g,
                        const float* __restrict__ b, float* __restrict__ h0, int Nn) {
    __shared__ float Ws[16 * HID];
    for (int i = threadIdx.x; i < 16 * HID; i += blockDim.x) Ws[i] = Win[i];
    __syncthreads();
    int gw = (blockIdx.x * blockDim.x + threadIdx.x) >> 5;
    if (gw >= Nn) return;
    int lane = threadIdx.x & 31;
    float4 bv = ((const float4*)bin)[lane];
    float acc0 = bv.x, acc1 = bv.y, acc2 = bv.z, acc3 = bv.w;
#pragma unroll
    for (int k = 0; k < 16; k++) {
        float xv = __ldg(x + (size_t)gw * 16 + k);
        acc0 += xv * Ws[k * HID + lane * 4 + 0];
        acc1 += xv * Ws[k * HID + lane * 4 + 1];
        acc2 += xv * Ws[k * HID + lane * 4 + 2];
        acc3 += xv * Ws[k * HID + lane * 4 + 3];
    }
    float t0 = fmaxf(acc0, 0.f), t1 = fmaxf(acc1, 0.f), t2 = fmaxf(acc2, 0.f), t3 = fmaxf(acc3, 0.f);
    float sm = warp_sum(t0 + t1 + t2 + t3);
    float sq = warp_sum(t0 * t0 + t1 * t1 + t2 * t2 + t3 * t3);
    float mu = sm * (1.f / 128.f);
    float var = sq * (1.f / 128.f) - mu * mu;
    float rs = rsqrtf(var + 1e-5f);
    float4 gv = ((const float4*)g)[lane];
    float4 bbv = ((const float4*)b)[lane];
    float4 o;
    o.x = (t0 - mu) * rs * gv.x + bbv.x;
    o.y = (t1 - mu) * rs * gv.y + bbv.y;
    o.z = (t2 - mu) * rs * gv.z + bbv.z;
    o.w = (t3 - mu) * rs * gv.w + bbv.w;
    ((float4*)(h0 + (size_t)gw * HID))[lane] = o;
}

// ---------------- HMMA GEMM: C[M,128] = A[M,128] @ W[128,128] via bf16x3 split ----
// MODE 0: C = hp, fused alpha_src/alpha_dst epilogue
// MODE 1: C = relu(D + bias)
// SMEM: Ahi/Alo/Bhi/Blo tiles, 272B row stride (bank-conflict-free fragment LDS).
#define RS 272
#define OFF_AHI 0
#define OFF_ALO 34816
#define OFF_BHI 69632
#define OFF_BLO 104448
#define OFF_ATT 139264
#define SM_TOT  140288

template <int MODE>
__global__ void __launch_bounds__(256) k_mma(
    const float* __restrict__ A, const __nv_bfloat16* __restrict__ BhG,
    const __nv_bfloat16* __restrict__ BlG, const float* __restrict__ v1,
    const float* __restrict__ v2, float* __restrict__ C,
    float* __restrict__ oAS, float* __restrict__ oAD, int M) {
    extern __shared__ char smem[];
    char* Ahi = smem + OFF_AHI;
    char* Alo = smem + OFF_ALO;
    char* Bhi = smem + OFF_BHI;
    char* Blo = smem + OFF_BLO;
    float* att = (float*)(smem + OFF_ATT);
    float* Cs = (float*)smem;  // reused after compute (row stride 132 floats)
    const int tid = threadIdx.x;
    const int m0 = blockIdx.x * 128;

    if (tid < 128) att[tid] = v1[tid];
    else if (MODE == 0) att[tid] = v2[tid - 128];

    // ---- fill A: fp32 -> bf16 hi/lo ----
#pragma unroll
    for (int it = 0; it < 8; it++) {
        int q = tid + it * 256;
        int r = q >> 4, w = q & 15;
        int m = m0 + r;
        float f[8];
        if (m < M) {
            const float* ar = A + (size_t)m * HID + w * 8;
            float4 x0 = *(const float4*)ar;
            float4 x1 = *(const float4*)(ar + 4);
            f[0] = x0.x; f[1] = x0.y; f[2] = x0.z; f[3] = x0.w;
            f[4] = x1.x; f[5] = x1.y; f[6] = x1.z; f[7] = x1.w;
        } else {
#pragma unroll
            for (int i = 0; i < 8; i++) f[i] = 0.f;
        }
        uint32_t hu[8], lu[8];
#pragma unroll
        for (int i = 0; i < 8; i++) {
            __nv_bfloat16 hb = __float2bfloat16(f[i]);
            float rr = f[i] - __bfloat162float(hb);
            hu[i] = (uint32_t)__bfloat16_as_ushort(hb);
            lu[i] = (uint32_t)__bfloat16_as_ushort(__float2bfloat16(rr));
        }
        uint4 ph, pl;
        ph.x = hu[0] | (hu[1] << 16); ph.y = hu[2] | (hu[3] << 16);
        ph.z = hu[4] | (hu[5] << 16); ph.w = hu[6] | (hu[7] << 16);
        pl.x = lu[0] | (lu[1] << 16); pl.y = lu[2] | (lu[3] << 16);
        pl.z = lu[4] | (lu[5] << 16); pl.w = lu[6] | (lu[7] << 16);
        *(uint4*)(Ahi + r * RS + w * 16) = ph;
        *(uint4*)(Alo + r * RS + w * 16) = pl;
    }
    // ---- fill B (already split in gmem, [n][k] packed 256B rows) ----
#pragma unroll
    for (int it = 0; it < 8; it++) {
        int q = tid + it * 256;
        int r = q >> 4, w = q & 15;
        *(uint4*)(Bhi + r * RS + w * 16) = *(const uint4*)((const char*)BhG + r * 256 + w * 16);
        *(uint4*)(Blo + r * RS + w * 16) = *(const uint4*)((const char*)BlG + r * 256 + w * 16);
    }
    __syncthreads();

    const int wid = tid >> 5, lane = tid & 31;
    const int cq = lane & 3, gq = lane >> 2;
    const int mb = (wid & 3) * 32;   // warp row base (32 rows)
    const int nb = (wid >> 2) * 64;  // warp col base (64 cols)

    float acc[2][8][4];
#pragma unroll
    for (int a = 0; a < 2; a++)
#pragma unroll
        for (int j = 0; j < 8; j++)
#pragma unroll
            for (int i = 0; i < 4; i++) acc[a][j][i] = 0.f;

    const uint32_t aoffb = (uint32_t)(mb + gq) * RS + cq * 4;
    const uint32_t boffb = (uint32_t)(nb + gq) * RS + cq * 4;

#pragma unroll
    for (int kc = 0; kc < 8; kc++) {
        const uint32_t kby = kc * 32;  // 16 bf16 = 32 bytes per chunk
        uint32_t ah[2][4], al[2][4];
#pragma unroll
        for (int mt = 0; mt < 2; mt++) {
            uint32_t base = aoffb + mt * (16 * RS) + kby;
            ah[mt][0] = *(const uint32_t*)(Ahi + base);
            ah[mt][1] = *(const uint32_t*)(Ahi + base + 8 * RS);
            ah[mt][2] = *(const uint32_t*)(Ahi + base + 16);
            ah[mt][3] = *(const uint32_t*)(Ahi + base + 8 * RS + 16);
            al[mt][0] = *(const uint32_t*)(Alo + base);
            al[mt][1] = *(const uint32_t*)(Alo + base + 8 * RS);
            al[mt][2] = *(const uint32_t*)(Alo + base + 16);
            al[mt][3] = *(const uint32_t*)(Alo + base + 8 * RS + 16);
        }
#pragma unroll
        for (int j = 0; j < 8; j++) {
            uint32_t bo = boffb + j * (8 * RS) + kby;
            uint32_t bh0 = *(const uint32_t*)(Bhi + bo);
            uint32_t bh1 = *(const uint32_t*)(Bhi + bo + 16);
            uint32_t bl0 = *(const uint32_t*)(Blo + bo);
            uint32_t bl1 = *(const uint32_t*)(Blo + bo + 16);
#pragma unroll
            for (int mt = 0; mt < 2; mt++) {
                mma16816(acc[mt][j], ah[mt][0], ah[mt][1], ah[mt][2], ah[mt][3], bh0, bh1);
                mma16816(acc[mt][j], al[mt][0], al[mt][1], al[mt][2], al[mt][3], bh0, bh1);
                mma16816(acc[mt][j], ah[mt][0], ah[mt][1], ah[mt][2], ah[mt][3], bl0, bl1);
            }
        }
    }

    // ---- fused alpha epilogue (MODE 0) ----
    if (MODE == 0) {
        float sAS[2][2][4], sAD[2][2][4];
#pragma unroll
        for (int a = 0; a < 2; a++)
#pragma unroll
            for (int hf = 0; hf < 2; hf++)
#pragma unroll
                for (int h = 0; h < 4; h++) { sAS[a][hf][h] = 0.f; sAD[a][hf][h] = 0.f; }
#pragma unroll
        for (int mt = 0; mt < 2; mt++)
#pragma unroll
            for (int j = 0; j < 8; j++) {
                int h = j >> 1;
                int col = nb + j * 8 + 2 * cq;
                float w0 = att[col], w1 = att[col + 1];
                float u0 = att[128 + col], u1 = att[128 + col + 1];
                sAS[mt][0][h] += acc[mt][j][0] * w0 + acc[mt][j][1] * w1;
                sAS[mt][1][h] += acc[mt][j][2] * w0 + acc[mt][j][3] * w1;
                sAD[mt][0][h] += acc[mt][j][0] * u0 + acc[mt][j][1] * u1;
                sAD[mt][1][h] += acc[mt][j][2] * u0 + acc[mt][j][3] * u1;
            }
#pragma unroll
        for (int mt = 0; mt < 2; mt++)
#pragma unroll
            for (int hf = 0; hf < 2; hf++)
#pragma unroll
                for (int h = 0; h < 4; h++) {
                    float v = sAS[mt][hf][h];
                    v += __shfl_xor_sync(0xffffffffu, v, 1);
                    v += __shfl_xor_sync(0xffffffffu, v, 2);
                    sAS[mt][hf][h] = v;
                    float u = sAD[mt][hf][h];
                    u += __shfl_xor_sync(0xffffffffu, u, 1);
                    u += __shfl_xor_sync(0xffffffffu, u, 2);
                    sAD[mt][hf][h] = u;
                }
        if (cq == 0) {
#pragma unroll
            for (int mt = 0; mt < 2; mt++)
#pragma unroll
                for (int hf = 0; hf < 2; hf++) {
                    int r = m0 + mb + mt * 16 + hf * 8 + gq;
                    if (r < M) {
                        *(float4*)(oAS + (size_t)r * 8 + (nb >> 4)) =
                            make_float4(sAS[mt][hf][0], sAS[mt][hf][1], sAS[mt][hf][2], sAS[mt][hf][3]);
                        *(float4*)(oAD + (size_t)r * 8 + (nb >> 4)) =
                            make_float4(sAD[mt][hf][0], sAD[mt][hf][1], sAD[mt][hf][2], sAD[mt][hf][3]);
                    }
                }
        }
    }

    // ---- stage C in SMEM, write coalesced ----
    __syncthreads();
#pragma unroll
    for (int mt = 0; mt < 2; mt++)
#pragma unroll
        for (int j = 0; j < 8; j++) {
            int row = mb + mt * 16 + gq;
            int col = nb + j * 8 + 2 * cq;
            *(float2*)(Cs + row * 132 + col) = make_float2(acc[mt][j][0], acc[mt][j][1]);
            *(float2*)(Cs + (row + 8) * 132 + col) = make_float2(acc[mt][j][2], acc[mt][j][3]);
        }
    __syncthreads();
#pragma unroll
    for (int it = 0; it < 16; it++) {
        int q = tid + it * 256;
        int r = q >> 5, w = q & 31;
        int m = m0 + r;
        if (m < M) {
            float4 v = *(float4*)(Cs + r * 132 + w * 4);
            if (MODE == 1) {
                v.x = fmaxf(v.x + att[w * 4 + 0], 0.f);
                v.y = fmaxf(v.y + att[w * 4 + 1], 0.f);
                v.z = fmaxf(v.z + att[w * 4 + 2], 0.f);
                v.w = fmaxf(v.w + att[w * 4 + 3], 0.f);
            }
            *(float4*)(C + (size_t)m * HID + w * 4) = v;
        }
    }
}

// ---------------- fused attention + aggregation + residual + LN ----------------
__global__ void k_gat_edge(const float* __restrict__ hcur, const float* __restrict__ weh_l,
                           const float* __restrict__ bgl, const float* __restrict__ lng,
                           const float* __restrict__ lnb, float* __restrict__ hnext, int Nn) {
    int gw = (blockIdx.x * blockDim.x + threadIdx.x) >> 5;
    if (gw >= Nn) return;
    int lane = threadIdx.x & 31;
    int hh = lane >> 2;
    float adv = __ldg(&g_ad[(size_t)gw * 8 + hh]);
    float w0 = __ldg(&weh_l[0 * 8 + hh]);
    float w1 = __ldg(&weh_l[1 * 8 + hh]);
    float w2 = __ldg(&weh_l[2 * 8 + hh]);
    float w3 = __ldg(&weh_l[3 * 8 + hh]);
    int s0 = g_off[gw], s1 = g_off[gw + 1];
    float ax = 0.f, ay = 0.f, az = 0.f, aw = 0.f, den = 0.f;
    for (int e = s0; e < s1; ++e) {
        int s = __ldg(&g_srcS[e]);
        float asv = __ldg(&g_as[(size_t)s * 8 + hh]);
        float4 eav = g_eaS[e];
        float al = asv + adv + eav.x * w0 + eav.y * w1 + eav.z * w2 + eav.w * w3;
        al = al > 0.f ? al : 0.2f * al;
        float a = __expf(al);
        den += a;
        float4 hv = *(const float4*)(g_hp + (size_t)s * HID + lane * 4);
        ax = fmaf(a, hv.x, ax);
        ay = fmaf(a, hv.y, ay);
        az = fmaf(a, hv.z, az);
        aw = fmaf(a, hv.w, aw);
    }
    float r = 1.f / (den + 1e-16f);
    float4 hc = *(const float4*)(hcur + (size_t)gw * HID + lane * 4);
    float4 bgv = ((const float4*)bgl)[lane];
    float t0 = hc.x + ax * r + bgv.x;
    float t1 = hc.y + ay * r + bgv.y;
    float t2 = hc.z + az * r + bgv.z;
    float t3 = hc.w + aw * r + bgv.w;
    float sm = warp_sum(t0 + t1 + t2 + t3);
    float sq = warp_sum(t0 * t0 + t1 * t1 + t2 * t2 + t3 * t3);
    float mu = sm * (1.f / 128.f);
    float var = sq * (1.f / 128.f) - mu * mu;
    float rs = rsqrtf(var + 1e-5f);
    float4 gv = ((const float4*)lng)[lane];
    float4 bbv = ((const float4*)lnb)[lane];
    float4 o;
    o.x = (t0 - mu) * rs * gv.x + bbv.x;
    o.y = (t1 - mu) * rs * gv.y + bbv.y;
    o.z = (t2 - mu) * rs * gv.z + bbv.z;
    o.w = (t3 - mu) * rs * gv.w + bbv.w;
    ((float4*)(hnext + (size_t)gw * HID))[lane] = o;
}

// ---------------- output head 2: out = relu(t @ W2 + b2), OUT_DIM=3 ----------------
__global__ void k_out2(const float* __restrict__ t, const float* __restrict__ W2,
                       const float* __restrict__ b2, float* __restrict__ out, int Nn) {
    __shared__ float w[HID * 3];
    for (int i = threadIdx.x; i < HID * 3; i += blockDim.x) w[i] = W2[i];
    __syncthreads();
    int gw = (blockIdx.x * blockDim.x + threadIdx.x) >> 5;
    if (gw >= Nn) return;
    int lane = threadIdx.x & 31;
    float p0 = 0.f, p1 = 0.f, p2 = 0.f;
#pragma unroll
    for (int i = 0; i < 4; i++) {
        int k = lane + 32 * i;
        float v = t[(size_t)gw * HID + k];
        p0 += v * w[k * 3 + 0];
        p1 += v * w[k * 3 + 1];
        p2 += v * w[k * 3 + 2];
    }
    p0 = warp_sum(p0); p1 = warp_sum(p1); p2 = warp_sum(p2);
    if (lane == 0) {
        out[(size_t)gw * 3 + 0] = fmaxf(p0 + __ldg(&b2[0]), 0.f);
        out[(size_t)gw * 3 + 1] = fmaxf(p1 + __ldg(&b2[1]), 0.f);
        out[(size_t)gw * 3 + 2] = fmaxf(p2 + __ldg(&b2[2]), 0.f);
    }
}

// ---------------- launch ----------------
extern "C" void kernel_launch(void* const* d_in, const int* in_sizes, int n_in,
                              void* d_out, int out_size) {
    const float* x = (const float*)d_in[0];
    const int* ei = (const int*)d_in[1];
    const float* ea = (const float*)d_in[2];
    const float* W_in = (const float*)d_in[3];
    const float* b_in = (const float*)d_in[4];
    const float* ln_in_g = (const float*)d_in[5];
    const float* ln_in_b = (const float*)d_in[6];
    const float* Wg = (const float*)d_in[7];
    const float* att_src = (const float*)d_in[8];
    const float* att_dst = (const float*)d_in[9];
    const float* We = (const float*)d_in[10];
    const float* att_edge = (const float*)d_in[11];
    const float* bg = (const float*)d_in[12];
    const float* ln_g = (const float*)d_in[13];
    const float* ln_b = (const float*)d_in[14];
    const float* W1 = (const float*)d_in[15];
    const float* b1 = (const float*)d_in[16];
    const float* W2 = (const float*)d_in[17];
    const float* b2 = (const float*)d_in[18];

    int Nn = in_sizes[0] / 16;   // 100000
    int Ee = in_sizes[2] / 4;    // 1600000

    float *hA, *hB, *hp, *weh, *as, *ad;
    __nv_bfloat16 *Bh, *Bl;
    cudaGetSymbolAddress((void**)&hA, g_hA);
    cudaGetSymbolAddress((void**)&hB, g_hB);
    cudaGetSymbolAddress((void**)&hp, g_hp);
    cudaGetSymbolAddress((void**)&weh, g_weh);
    cudaGetSymbolAddress((void**)&as, g_as);
    cudaGetSymbolAddress((void**)&ad, g_ad);
    cudaGetSymbolAddress((void**)&Bh, g_Bh);
    cudaGetSymbolAddress((void**)&Bl, g_Bl);

    cudaFuncSetAttribute(k_mma<0>, cudaFuncAttributeMaxDynamicSharedMemorySize, SM_TOT);
    cudaFuncSetAttribute(k_mma<1>, cudaFuncAttributeMaxDynamicSharedMemorySize, SM_TOT);

    // ---- preprocessing: CSR by dst, deterministic order ----
    k_zero<<<(Nn + 255) / 256, 256>>>(Nn);
    k_hist<<<(Ee + 255) / 256, 256>>>(ei, Ee);
    int nb = (Nn + 1023) / 1024;
    k_scan1<<<nb, 1024>>>(Nn);
    k_scan2<<<1, 1>>>(nb);
    k_scan3<<<nb, 1024>>>(Nn);
    k_scatter<<<(Ee + 255) / 256, 256>>>(ei, Ee);
    k_sortfix<<<(Nn + 255) / 256, 256>>>(ei, (const float4*)ea, Nn);

    // ---- weight prep ----
    k_prep_weh<<<NLAYERS, 32>>>(We, att_edge);
    k_prep_bsplit<<<NLAYERS + 1, 128>>>(Wg, W1);

    // ---- input projection ----
    int nwb = (Nn + 7) / 8;
    k_input<<<nwb, 256>>>(x, W_in, b_in, ln_in_g, ln_in_b, hA, Nn);

    // ---- GAT layers ----
    float* hcur = hA;
    float* hnxt = hB;
    int mb = (Nn + 127) / 128;
    for (int l = 0; l < NLAYERS; l++) {
        k_mma<0><<<mb, 256, SM_TOT>>>(hcur, Bh + (size_t)l * HID * HID,
                                      Bl + (size_t)l * HID * HID,
                                      att_src + l * HID, att_dst + l * HID,
                                      hp, as, ad, Nn);
        k_gat_edge<<<nwb, 256>>>(hcur, weh + l * 32, bg + l * HID,
                                 ln_g + l * HID, ln_b + l * HID, hnxt, Nn);
        float* t = hcur; hcur = hnxt; hnxt = t;
    }

    // ---- output head ----
    k_mma<1><<<mb, 256, SM_TOT>>>(hcur, Bh + (size_t)NLAYERS * HID * HID,
                                  Bl + (size_t)NLAYERS * HID * HID,
                                  b1, b1, hp, nullptr, nullptr, Nn);
    k_out2<<<nwb, 256>>>(hp, W2, b2, (float*)d_out, Nn);
}

// round 4
// speedup vs baseline: 1.6479x; 1.0780x over previous
#include <cuda_runtime.h>
#include <cuda_bf16.h>
#include <cuda_fp16.h>
#include <cstdint>

#define NMAX 100000
#define EMAX 1600000
#define HID 128
#define HEADS 8
#define NLAYERS 6

// ---------------- scratch (device globals; no allocation allowed) ----------------
__device__ __align__(16) float g_hA[(size_t)NMAX * HID];
__device__ __align__(16) float g_hB[(size_t)NMAX * HID];
__device__ __align__(16) float g_hp[(size_t)NMAX * HID];       // fp32 staging (output head)
__device__ __align__(16) __half g_hp16[(size_t)NMAX * HID];    // fp16 messages
__device__ __align__(16) __half g_as16[(size_t)NMAX * HEADS];  // fp16 alpha_src
__device__ __align__(16) float g_ad[(size_t)NMAX * HEADS];     // fp32 alpha_dst (per-node)
__device__ int g_off[NMAX + 1];
__device__ int g_deg[NMAX];
__device__ int g_cnt[NMAX];
__device__ int g_bsum[256];
__device__ int g_eid[EMAX];
__device__ int g_srcS[EMAX];
__device__ __align__(8) uint2 g_eaS2[EMAX];  // half4 edge attrs, dst-sorted
__device__ float g_weh[NLAYERS * 4 * HEADS];
// pre-split transposed weights: [7][n=128][k=128] bf16 (6 GAT layers + W1)
__device__ __align__(16) __nv_bfloat16 g_Bh[7 * 128 * 128];
__device__ __align__(16) __nv_bfloat16 g_Bl[7 * 128 * 128];

// ---------------- utils ----------------
__device__ __forceinline__ float warp_sum(float v) {
#pragma unroll
    for (int o = 16; o; o >>= 1) v += __shfl_xor_sync(0xffffffffu, v, o);
    return v;
}

__device__ __forceinline__ void mma16816(float* d, uint32_t a0, uint32_t a1, uint32_t a2,
                                         uint32_t a3, uint32_t b0, uint32_t b1) {
    asm volatile(
        "mma.sync.aligned.m16n8k16.row.col.f32.bf16.bf16.f32 "
        "{%0,%1,%2,%3}, {%4,%5,%6,%7}, {%8,%9}, {%0,%1,%2,%3};"
        : "+f"(d[0]), "+f"(d[1]), "+f"(d[2]), "+f"(d[3])
        : "r"(a0), "r"(a1), "r"(a2), "r"(a3), "r"(b0), "r"(b1));
}

// ---------------- preprocessing ----------------
__global__ void k_zero(int n) {
    int i = blockIdx.x * blockDim.x + threadIdx.x;
    if (i < n) { g_deg[i] = 0; g_cnt[i] = 0; }
}

__global__ void k_hist(const int* __restrict__ ei, int Ee) {
    int e = blockIdx.x * blockDim.x + threadIdx.x;
    if (e < Ee) atomicAdd(&g_deg[ei[Ee + e]], 1);
}

__global__ void k_scan1(int n) {
    __shared__ int ws[32];
    int i = blockIdx.x * 1024 + threadIdx.x;
    int lane = threadIdx.x & 31, wid = threadIdx.x >> 5;
    int v = (i < n) ? g_deg[i] : 0;
    int x = v;
#pragma unroll
    for (int o = 1; o < 32; o <<= 1) {
        int y = __shfl_up_sync(0xffffffffu, x, o);
        if (lane >= o) x += y;
    }
    if (lane == 31) ws[wid] = x;
    __syncthreads();
    if (wid == 0) {
        int y = ws[lane];
#pragma unroll
        for (int o = 1; o < 32; o <<= 1) {
            int z = __shfl_up_sync(0xffffffffu, y, o);
            if (lane >= o) y += z;
        }
        ws[lane] = y;
    }
    __syncthreads();
    int inc = x + (wid > 0 ? ws[wid - 1] : 0);
    if (i < n) g_off[i] = inc - v;
    if (threadIdx.x == 1023) g_bsum[blockIdx.x] = inc;
}

__global__ void k_scan2(int nb) {
    int run = 0;
    for (int b = 0; b < nb; b++) { int t = g_bsum[b]; g_bsum[b] = run; run += t; }
    g_bsum[nb] = run;
}

__global__ void k_scan3(int n) {
    int i = blockIdx.x * 1024 + threadIdx.x;
    if (i < n) g_off[i] += g_bsum[blockIdx.x];
    if (i == 0) g_off[n] = g_bsum[gridDim.x];
}

__global__ void k_scatter(const int* __restrict__ ei, int Ee) {
    int e = blockIdx.x * blockDim.x + threadIdx.x;
    if (e >= Ee) return;
    int d = ei[Ee + e];
    int p = g_off[d] + atomicAdd(&g_cnt[d], 1);
    g_eid[p] = e;
}

__device__ __forceinline__ uint2 pack_half4(float4 v) {
    __half2 p0 = __floats2half2_rn(v.x, v.y);
    __half2 p1 = __floats2half2_rn(v.z, v.w);
    uint2 u;
    u.x = *reinterpret_cast<uint32_t*>(&p0);
    u.y = *reinterpret_cast<uint32_t*>(&p1);
    return u;
}

__global__ void k_sortfix(const int* __restrict__ ei, const float4* __restrict__ ea, int Nn) {
    int n = blockIdx.x * blockDim.x + threadIdx.x;
    if (n >= Nn) return;
    int st = g_off[n], en = g_off[n + 1];
    int d = en - st;
    if (d <= 0) return;
    if (d <= 192) {
        int a[192];
        for (int i = 0; i < d; i++) a[i] = g_eid[st + i];
        for (int i = 1; i < d; i++) {
            int key = a[i]; int j = i - 1;
            while (j >= 0 && a[j] > key) { a[j + 1] = a[j]; j--; }
            a[j + 1] = key;
        }
        for (int i = 0; i < d; i++) {
            int eid = a[i];
            g_srcS[st + i] = ei[eid];
            g_eaS2[st + i] = pack_half4(ea[eid]);
        }
    } else {
        for (int i = 0; i < d - 1; i++) {
            int mn = i;
            for (int j = i + 1; j < d; j++)
                if (g_eid[st + j] < g_eid[st + mn]) mn = j;
            int t = g_eid[st + i]; g_eid[st + i] = g_eid[st + mn]; g_eid[st + mn] = t;
        }
        for (int i = 0; i < d; i++) {
            int eid = g_eid[st + i];
            g_srcS[st + i] = ei[eid];
            g_eaS2[st + i] = pack_half4(ea[eid]);
        }
    }
}

// edge attention weights folded per layer
__global__ void k_prep_weh(const float* __restrict__ We, const float* __restrict__ aev) {
    int l = blockIdx.x;
    int t = threadIdx.x;  // 32
    int d = t >> 3, h = t & 7;
    float s = 0.f;
#pragma unroll
    for (int c = 0; c < 16; c++)
        s += We[l * 4 * HID + d * HID + h * 16 + c] * aev[l * HID + h * 16 + c];
    g_weh[l * 32 + d * 8 + h] = s;
}

// transpose + bf16-split weights
__global__ void k_prep_bsplit(const float* __restrict__ Wg, const float* __restrict__ W1) {
    int l = blockIdx.x;
    const float* W = (l < NLAYERS) ? (Wg + (size_t)l * HID * HID) : W1;
    int n = threadIdx.x;
    __nv_bfloat16* bh = g_Bh + (size_t)l * HID * HID;
    __nv_bfloat16* bl = g_Bl + (size_t)l * HID * HID;
    for (int k = 0; k < HID; k++) {
        float v = W[k * HID + n];
        __nv_bfloat16 hb = __float2bfloat16(v);
        float r = v - __bfloat162float(hb);
        bh[n * HID + k] = hb;
        bl[n * HID + k] = __float2bfloat16(r);
    }
}

// ---------------- input projection: h0 = LN(relu(x @ W_in + b_in)) ----------------
__global__ void k_input(const float* __restrict__ x, const float* __restrict__ Win,
                        const float* __restrict__ bin, const float* __restrict__ g,
                        const float* __restrict__ b, float* __restrict__ h0, int Nn) {
    __shared__ float Ws[16 * HID];
    for (int i = threadIdx.x; i < 16 * HID; i += blockDim.x) Ws[i] = Win[i];
    __syncthreads();
    int gw = (blockIdx.x * blockDim.x + threadIdx.x) >> 5;
    if (gw >= Nn) return;
    int lane = threadIdx.x & 31;
    float4 bv = ((const float4*)bin)[lane];
    float acc0 = bv.x, acc1 = bv.y, acc2 = bv.z, acc3 = bv.w;
#pragma unroll
    for (int k = 0; k < 16; k++) {
        float xv = __ldg(x + (size_t)gw * 16 + k);
        acc0 += xv * Ws[k * HID + lane * 4 + 0];
        acc1 += xv * Ws[k * HID + lane * 4 + 1];
        acc2 += xv * Ws[k * HID + lane * 4 + 2];
        acc3 += xv * Ws[k * HID + lane * 4 + 3];
    }
    float t0 = fmaxf(acc0, 0.f), t1 = fmaxf(acc1, 0.f), t2 = fmaxf(acc2, 0.f), t3 = fmaxf(acc3, 0.f);
    float sm = warp_sum(t0 + t1 + t2 + t3);
    float sq = warp_sum(t0 * t0 + t1 * t1 + t2 * t2 + t3 * t3);
    float mu = sm * (1.f / 128.f);
    float var = sq * (1.f / 128.f) - mu * mu;
    float rs = rsqrtf(var + 1e-5f);
    float4 gv = ((const float4*)g)[lane];
    float4 bbv = ((const float4*)b)[lane];
    float4 o;
    o.x = (t0 - mu) * rs * gv.x + bbv.x;
    o.y = (t1 - mu) * rs * gv.y + bbv.y;
    o.z = (t2 - mu) * rs * gv.z + bbv.z;
    o.w = (t3 - mu) * rs * gv.w + bbv.w;
    ((float4*)(h0 + (size_t)gw * HID))[lane] = o;
}

// ---------------- HMMA GEMM: C[M,128] = A[M,128] @ W[128,128] via bf16x3 split ----
// MODE 0: C -> fp16 hp, fused fp16 alpha_src + fp32 alpha_dst epilogue
// MODE 1: C -> fp32, relu(D + bias)
#define RS 272
#define OFF_AHI 0
#define OFF_ALO 34816
#define OFF_BHI 69632
#define OFF_BLO 104448
#define OFF_ATT 139264
#define SM_TOT  140288

template <int MODE>
__global__ void __launch_bounds__(256) k_mma(
    const float* __restrict__ A, const __nv_bfloat16* __restrict__ BhG,
    const __nv_bfloat16* __restrict__ BlG, const float* __restrict__ v1,
    const float* __restrict__ v2, float* __restrict__ Cf, __half* __restrict__ Ch,
    __half* __restrict__ oAS, float* __restrict__ oAD, int M) {
    extern __shared__ char smem[];
    char* Ahi = smem + OFF_AHI;
    char* Alo = smem + OFF_ALO;
    char* Bhi = smem + OFF_BHI;
    char* Blo = smem + OFF_BLO;
    float* att = (float*)(smem + OFF_ATT);
    float* Cs = (float*)smem;  // reused after compute (row stride 132 floats)
    const int tid = threadIdx.x;
    const int m0 = blockIdx.x * 128;

    if (tid < 128) att[tid] = v1[tid];
    else if (MODE == 0) att[tid] = v2[tid - 128];

    // ---- fill A: fp32 -> bf16 hi/lo ----
#pragma unroll
    for (int it = 0; it < 8; it++) {
        int q = tid + it * 256;
        int r = q >> 4, w = q & 15;
        int m = m0 + r;
        float f[8];
        if (m < M) {
            const float* ar = A + (size_t)m * HID + w * 8;
            float4 x0 = *(const float4*)ar;
            float4 x1 = *(const float4*)(ar + 4);
            f[0] = x0.x; f[1] = x0.y; f[2] = x0.z; f[3] = x0.w;
            f[4] = x1.x; f[5] = x1.y; f[6] = x1.z; f[7] = x1.w;
        } else {
#pragma unroll
            for (int i = 0; i < 8; i++) f[i] = 0.f;
        }
        uint32_t hu[8], lu[8];
#pragma unroll
        for (int i = 0; i < 8; i++) {
            __nv_bfloat16 hb = __float2bfloat16(f[i]);
            float rr = f[i] - __bfloat162float(hb);
            hu[i] = (uint32_t)__bfloat16_as_ushort(hb);
            lu[i] = (uint32_t)__bfloat16_as_ushort(__float2bfloat16(rr));
        }
        uint4 ph, pl;
        ph.x = hu[0] | (hu[1] << 16); ph.y = hu[2] | (hu[3] << 16);
        ph.z = hu[4] | (hu[5] << 16); ph.w = hu[6] | (hu[7] << 16);
        pl.x = lu[0] | (lu[1] << 16); pl.y = lu[2] | (lu[3] << 16);
        pl.z = lu[4] | (lu[5] << 16); pl.w = lu[6] | (lu[7] << 16);
        *(uint4*)(Ahi + r * RS + w * 16) = ph;
        *(uint4*)(Alo + r * RS + w * 16) = pl;
    }
    // ---- fill B (pre-split bf16 [n][k], 256B rows) ----
#pragma unroll
    for (int it = 0; it < 8; it++) {
        int q = tid + it * 256;
        int r = q >> 4, w = q & 15;
        *(uint4*)(Bhi + r * RS + w * 16) = *(const uint4*)((const char*)BhG + r * 256 + w * 16);
        *(uint4*)(Blo + r * RS + w * 16) = *(const uint4*)((const char*)BlG + r * 256 + w * 16);
    }
    __syncthreads();

    const int wid = tid >> 5, lane = tid & 31;
    const int cq = lane & 3, gq = lane >> 2;
    const int mb = (wid & 3) * 32;
    const int nb = (wid >> 2) * 64;

    float acc[2][8][4];
#pragma unroll
    for (int a = 0; a < 2; a++)
#pragma unroll
        for (int j = 0; j < 8; j++)
#pragma unroll
            for (int i = 0; i < 4; i++) acc[a][j][i] = 0.f;

    const uint32_t aoffb = (uint32_t)(mb + gq) * RS + cq * 4;
    const uint32_t boffb = (uint32_t)(nb + gq) * RS + cq * 4;

#pragma unroll
    for (int kc = 0; kc < 8; kc++) {
        const uint32_t kby = kc * 32;
        uint32_t ah[2][4], al[2][4];
#pragma unroll
        for (int mt = 0; mt < 2; mt++) {
            uint32_t base = aoffb + mt * (16 * RS) + kby;
            ah[mt][0] = *(const uint32_t*)(Ahi + base);
            ah[mt][1] = *(const uint32_t*)(Ahi + base + 8 * RS);
            ah[mt][2] = *(const uint32_t*)(Ahi + base + 16);
            ah[mt][3] = *(const uint32_t*)(Ahi + base + 8 * RS + 16);
            al[mt][0] = *(const uint32_t*)(Alo + base);
            al[mt][1] = *(const uint32_t*)(Alo + base + 8 * RS);
            al[mt][2] = *(const uint32_t*)(Alo + base + 16);
            al[mt][3] = *(const uint32_t*)(Alo + base + 8 * RS + 16);
        }
#pragma unroll
        for (int j = 0; j < 8; j++) {
            uint32_t bo = boffb + j * (8 * RS) + kby;
            uint32_t bh0 = *(const uint32_t*)(Bhi + bo);
            uint32_t bh1 = *(const uint32_t*)(Bhi + bo + 16);
            uint32_t bl0 = *(const uint32_t*)(Blo + bo);
            uint32_t bl1 = *(const uint32_t*)(Blo + bo + 16);
#pragma unroll
            for (int mt = 0; mt < 2; mt++) {
                mma16816(acc[mt][j], ah[mt][0], ah[mt][1], ah[mt][2], ah[mt][3], bh0, bh1);
                mma16816(acc[mt][j], al[mt][0], al[mt][1], al[mt][2], al[mt][3], bh0, bh1);
                mma16816(acc[mt][j], ah[mt][0], ah[mt][1], ah[mt][2], ah[mt][3], bl0, bl1);
            }
        }
    }

    // ---- fused alpha epilogue (MODE 0): alpha_src -> fp16, alpha_dst -> fp32 ----
    if (MODE == 0) {
        float sAS[2][2][4], sAD[2][2][4];
#pragma unroll
        for (int a = 0; a < 2; a++)
#pragma unroll
            for (int hf = 0; hf < 2; hf++)
#pragma unroll
                for (int h = 0; h < 4; h++) { sAS[a][hf][h] = 0.f; sAD[a][hf][h] = 0.f; }
#pragma unroll
        for (int mt = 0; mt < 2; mt++)
#pragma unroll
            for (int j = 0; j < 8; j++) {
                int h = j >> 1;
                int col = nb + j * 8 + 2 * cq;
                float w0 = att[col], w1 = att[col + 1];
                float u0 = att[128 + col], u1 = att[128 + col + 1];
                sAS[mt][0][h] += acc[mt][j][0] * w0 + acc[mt][j][1] * w1;
                sAS[mt][1][h] += acc[mt][j][2] * w0 + acc[mt][j][3] * w1;
                sAD[mt][0][h] += acc[mt][j][0] * u0 + acc[mt][j][1] * u1;
                sAD[mt][1][h] += acc[mt][j][2] * u0 + acc[mt][j][3] * u1;
            }
#pragma unroll
        for (int mt = 0; mt < 2; mt++)
#pragma unroll
            for (int hf = 0; hf < 2; hf++)
#pragma unroll
                for (int h = 0; h < 4; h++) {
                    float v = sAS[mt][hf][h];
                    v += __shfl_xor_sync(0xffffffffu, v, 1);
                    v += __shfl_xor_sync(0xffffffffu, v, 2);
                    sAS[mt][hf][h] = v;
                    float u = sAD[mt][hf][h];
                    u += __shfl_xor_sync(0xffffffffu, u, 1);
                    u += __shfl_xor_sync(0xffffffffu, u, 2);
                    sAD[mt][hf][h] = u;
                }
        if (cq == 0) {
#pragma unroll
            for (int mt = 0; mt < 2; mt++)
#pragma unroll
                for (int hf = 0; hf < 2; hf++) {
                    int r = m0 + mb + mt * 16 + hf * 8 + gq;
                    if (r < M) {
                        __half2 p0 = __floats2half2_rn(sAS[mt][hf][0], sAS[mt][hf][1]);
                        __half2 p1 = __floats2half2_rn(sAS[mt][hf][2], sAS[mt][hf][3]);
                        uint2 u;
                        u.x = *reinterpret_cast<uint32_t*>(&p0);
                        u.y = *reinterpret_cast<uint32_t*>(&p1);
                        *(uint2*)(oAS + (size_t)r * 8 + (nb >> 4)) = u;
                        *(float4*)(oAD + (size_t)r * 8 + (nb >> 4)) =
                            make_float4(sAD[mt][hf][0], sAD[mt][hf][1], sAD[mt][hf][2], sAD[mt][hf][3]);
                    }
                }
        }
    }

    // ---- stage C in SMEM, write coalesced ----
    __syncthreads();
#pragma unroll
    for (int mt = 0; mt < 2; mt++)
#pragma unroll
        for (int j = 0; j < 8; j++) {
            int row = mb + mt * 16 + gq;
            int col = nb + j * 8 + 2 * cq;
            *(float2*)(Cs + row * 132 + col) = make_float2(acc[mt][j][0], acc[mt][j][1]);
            *(float2*)(Cs + (row + 8) * 132 + col) = make_float2(acc[mt][j][2], acc[mt][j][3]);
        }
    __syncthreads();
#pragma unroll
    for (int it = 0; it < 16; it++) {
        int q = tid + it * 256;
        int r = q >> 5, w = q & 31;
        int m = m0 + r;
        if (m < M) {
            float4 v = *(float4*)(Cs + r * 132 + w * 4);
            if (MODE == 1) {
                v.x = fmaxf(v.x + att[w * 4 + 0], 0.f);
                v.y = fmaxf(v.y + att[w * 4 + 1], 0.f);
                v.z = fmaxf(v.z + att[w * 4 + 2], 0.f);
                v.w = fmaxf(v.w + att[w * 4 + 3], 0.f);
                *(float4*)(Cf + (size_t)m * HID + w * 4) = v;
            } else {
                __half2 p0 = __floats2half2_rn(v.x, v.y);
                __half2 p1 = __floats2half2_rn(v.z, v.w);
                uint2 u;
                u.x = *reinterpret_cast<uint32_t*>(&p0);
                u.y = *reinterpret_cast<uint32_t*>(&p1);
                *(uint2*)(Ch + (size_t)m * HID + w * 4) = u;
            }
        }
    }
}

// ---------------- fused attention + aggregation + residual + LN ----------------
__global__ void k_gat_edge(const float* __restrict__ hcur, const float* __restrict__ weh_l,
                           const float* __restrict__ bgl, const float* __restrict__ lng,
                           const float* __restrict__ lnb, float* __restrict__ hnext, int Nn) {
    int gw = (blockIdx.x * blockDim.x + threadIdx.x) >> 5;
    if (gw >= Nn) return;
    int lane = threadIdx.x & 31;
    int hh = lane >> 2;
    float adv = __ldg(&g_ad[(size_t)gw * 8 + hh]);
    float w0 = __ldg(&weh_l[0 * 8 + hh]);
    float w1 = __ldg(&weh_l[1 * 8 + hh]);
    float w2 = __ldg(&weh_l[2 * 8 + hh]);
    float w3 = __ldg(&weh_l[3 * 8 + hh]);
    int s0 = g_off[gw], s1 = g_off[gw + 1];
    float ax = 0.f, ay = 0.f, az = 0.f, aw = 0.f, den = 0.f;
    int sP = 0; uint2 eaP = make_uint2(0, 0);
    if (s0 < s1) { sP = __ldg(&g_srcS[s0]); eaP = g_eaS2[s0]; }
    for (int e = s0; e < s1; ++e) {
        int s = sP; uint2 eau = eaP;
        if (e + 1 < s1) { sP = __ldg(&g_srcS[e + 1]); eaP = g_eaS2[e + 1]; }
        float asv = __half2float(g_as16[(size_t)s * 8 + hh]);
        __half2 e01 = *reinterpret_cast<__half2*>(&eau.x);
        __half2 e23 = *reinterpret_cast<__half2*>(&eau.y);
        float2 f01 = __half22float2(e01);
        float2 f23 = __half22float2(e23);
        float al = asv + adv + f01.x * w0 + f01.y * w1 + f23.x * w2 + f23.y * w3;
        al = al > 0.f ? al : 0.2f * al;
        float a = __expf(al);
        den += a;
        uint2 hv = *(const uint2*)(g_hp16 + (size_t)s * HID + lane * 4);
        __half2 h01 = *reinterpret_cast<__half2*>(&hv.x);
        __half2 h23 = *reinterpret_cast<__half2*>(&hv.y);
        float2 g01 = __half22float2(h01);
        float2 g23 = __half22float2(h23);
        ax = fmaf(a, g01.x, ax);
        ay = fmaf(a, g01.y, ay);
        az = fmaf(a, g23.x, az);
        aw = fmaf(a, g23.y, aw);
    }
    float r = 1.f / (den + 1e-16f);
    float4 hc = *(const float4*)(hcur + (size_t)gw * HID + lane * 4);
    float4 bgv = ((const float4*)bgl)[lane];
    float t0 = hc.x + ax * r + bgv.x;
    float t1 = hc.y + ay * r + bgv.y;
    float t2 = hc.z + az * r + bgv.z;
    float t3 = hc.w + aw * r + bgv.w;
    float sm = warp_sum(t0 + t1 + t2 + t3);
    float sq = warp_sum(t0 * t0 + t1 * t1 + t2 * t2 + t3 * t3);
    float mu = sm * (1.f / 128.f);
    float var = sq * (1.f / 128.f) - mu * mu;
    float rs = rsqrtf(var + 1e-5f);
    float4 gv = ((const float4*)lng)[lane];
    float4 bbv = ((const float4*)lnb)[lane];
    float4 o;
    o.x = (t0 - mu) * rs * gv.x + bbv.x;
    o.y = (t1 - mu) * rs * gv.y + bbv.y;
    o.z = (t2 - mu) * rs * gv.z + bbv.z;
    o.w = (t3 - mu) * rs * gv.w + bbv.w;
    ((float4*)(hnext + (size_t)gw * HID))[lane] = o;
}

// ---------------- output head 2: out = relu(t @ W2 + b2), OUT_DIM=3 ----------------
__global__ void k_out2(const float* __restrict__ t, const float* __restrict__ W2,
                       const float* __restrict__ b2, float* __restrict__ out, int Nn) {
    __shared__ float w[HID * 3];
    for (int i = threadIdx.x; i < HID * 3; i += blockDim.x) w[i] = W2[i];
    __syncthreads();
    int gw = (blockIdx.x * blockDim.x + threadIdx.x) >> 5;
    if (gw >= Nn) return;
    int lane = threadIdx.x & 31;
    float p0 = 0.f, p1 = 0.f, p2 = 0.f;
#pragma unroll
    for (int i = 0; i < 4; i++) {
        int k = lane + 32 * i;
        float v = t[(size_t)gw * HID + k];
        p0 += v * w[k * 3 + 0];
        p1 += v * w[k * 3 + 1];
        p2 += v * w[k * 3 + 2];
    }
    p0 = warp_sum(p0); p1 = warp_sum(p1); p2 = warp_sum(p2);
    if (lane == 0) {
        out[(size_t)gw * 3 + 0] = fmaxf(p0 + __ldg(&b2[0]), 0.f);
        out[(size_t)gw * 3 + 1] = fmaxf(p1 + __ldg(&b2[1]), 0.f);
        out[(size_t)gw * 3 + 2] = fmaxf(p2 + __ldg(&b2[2]), 0.f);
    }
}

// ---------------- launch ----------------
extern "C" void kernel_launch(void* const* d_in, const int* in_sizes, int n_in,
                              void* d_out, int out_size) {
    const float* x = (const float*)d_in[0];
    const int* ei = (const int*)d_in[1];
    const float* ea = (const float*)d_in[2];
    const float* W_in = (const float*)d_in[3];
    const float* b_in = (const float*)d_in[4];
    const float* ln_in_g = (const float*)d_in[5];
    const float* ln_in_b = (const float*)d_in[6];
    const float* Wg = (const float*)d_in[7];
    const float* att_src = (const float*)d_in[8];
    const float* att_dst = (const float*)d_in[9];
    const float* We = (const float*)d_in[10];
    const float* att_edge = (const float*)d_in[11];
    const float* bg = (const float*)d_in[12];
    const float* ln_g = (const float*)d_in[13];
    const float* ln_b = (const float*)d_in[14];
    const float* W1 = (const float*)d_in[15];
    const float* b1 = (const float*)d_in[16];
    const float* W2 = (const float*)d_in[17];
    const float* b2 = (const float*)d_in[18];

    int Nn = in_sizes[0] / 16;   // 100000
    int Ee = in_sizes[2] / 4;    // 1600000

    float *hA, *hB, *hp, *weh, *ad;
    __half *hp16, *as16;
    __nv_bfloat16 *Bh, *Bl;
    cudaGetSymbolAddress((void**)&hA, g_hA);
    cudaGetSymbolAddress((void**)&hB, g_hB);
    cudaGetSymbolAddress((void**)&hp, g_hp);
    cudaGetSymbolAddress((void**)&hp16, g_hp16);
    cudaGetSymbolAddress((void**)&weh, g_weh);
    cudaGetSymbolAddress((void**)&as16, g_as16);
    cudaGetSymbolAddress((void**)&ad, g_ad);
    cudaGetSymbolAddress((void**)&Bh, g_Bh);
    cudaGetSymbolAddress((void**)&Bl, g_Bl);

    cudaFuncSetAttribute(k_mma<0>, cudaFuncAttributeMaxDynamicSharedMemorySize, SM_TOT);
    cudaFuncSetAttribute(k_mma<1>, cudaFuncAttributeMaxDynamicSharedMemorySize, SM_TOT);

    // ---- preprocessing: CSR by dst, deterministic order ----
    k_zero<<<(Nn + 255) / 256, 256>>>(Nn);
    k_hist<<<(Ee + 255) / 256, 256>>>(ei, Ee);
    int nb = (Nn + 1023) / 1024;
    k_scan1<<<nb, 1024>>>(Nn);
    k_scan2<<<1, 1>>>(nb);
    k_scan3<<<nb, 1024>>>(Nn);
    k_scatter<<<(Ee + 255) / 256, 256>>>(ei, Ee);
    k_sortfix<<<(Nn + 255) / 256, 256>>>(ei, (const float4*)ea, Nn);

    // ---- weight prep ----
    k_prep_weh<<<NLAYERS, 32>>>(We, att_edge);
    k_prep_bsplit<<<NLAYERS + 1, 128>>>(Wg, W1);

    // ---- input projection ----
    int nwb = (Nn + 7) / 8;
    k_input<<<nwb, 256>>>(x, W_in, b_in, ln_in_g, ln_in_b, hA, Nn);

    // ---- GAT layers ----
    float* hcur = hA;
    float* hnxt = hB;
    int mb = (Nn + 127) / 128;
    for (int l = 0; l < NLAYERS; l++) {
        k_mma<0><<<mb, 256, SM_TOT>>>(hcur, Bh + (size_t)l * HID * HID,
                                      Bl + (size_t)l * HID * HID,
                                      att_src + l * HID, att_dst + l * HID,
                                      nullptr, hp16, as16, ad, Nn);
        k_gat_edge<<<nwb, 256>>>(hcur, weh + l * 32, bg + l * HID,
                                 ln_g + l * HID, ln_b + l * HID, hnxt, Nn);
        float* t = hcur; hcur = hnxt; hnxt = t;
    }

    // ---- output head ----
    k_mma<1><<<mb, 256, SM_TOT>>>(hcur, Bh + (size_t)NLAYERS * HID * HID,
                                  Bl + (size_t)NLAYERS * HID * HID,
                                  b1, b1, hp, nullptr, nullptr, nullptr, Nn);
    k_out2<<<nwb, 256>>>(hp, W2, b2, (float*)d_out, Nn);
}